// round 5
// baseline (speedup 1.0000x reference)
#include <cuda_runtime.h>
#include <cstdint>

#define N_NODES 50000
#define N_EDGES 800000
#define D_IN    128
#define D_HID   128
#define D_MLP   256
#define D_OUT   10

// ---------------- scratch (static device globals: no allocations) ----------
__device__ float g_dis[N_NODES];             // deg^{-1/2}
__device__ int   g_cnt[N_NODES];             // in-degree counts (no self-loop)
__device__ int   g_cur[N_NODES];             // fill cursors
__device__ int   g_rowoff[N_NODES + 1];      // CSR row offsets (by dst)
__device__ int   g_csrc[N_EDGES];            // CSR src indices
__device__ float g_t [N_NODES * D_HID];      // t = h @ W (pre-aggregation)
__device__ float g_h [N_NODES * D_HID];      // aggregated hidden
__device__ float g_h2[N_NODES * D_MLP];      // MLP hidden

// ---------------- CSR build ----------------
__global__ void k_zero(int* __restrict__ cnt, int* __restrict__ cur) {
    int i = blockIdx.x * blockDim.x + threadIdx.x;
    if (i < N_NODES) { cnt[i] = 0; cur[i] = 0; }
}

__global__ void k_count(const int* __restrict__ ei, int* __restrict__ cnt) {
    int e = blockIdx.x * blockDim.x + threadIdx.x;
    if (e < N_EDGES) atomicAdd(&cnt[ei[N_EDGES + e]], 1);
}

__global__ void __launch_bounds__(1024) k_scan(
    const int* __restrict__ cnt, int* __restrict__ rowoff, float* __restrict__ dis)
{
    __shared__ int part[1024];
    const int PER = (N_NODES + 1023) / 1024;    // 49
    int t = threadIdx.x;
    int base = t * PER;

    int sum = 0;
    for (int i = 0; i < PER; i++) {
        int idx = base + i;
        if (idx < N_NODES) sum += cnt[idx];
    }
    part[t] = sum;
    __syncthreads();
    for (int off = 1; off < 1024; off <<= 1) {
        int v = (t >= off) ? part[t - off] : 0;
        __syncthreads();
        part[t] += v;
        __syncthreads();
    }
    int running = (t == 0) ? 0 : part[t - 1];
    for (int i = 0; i < PER; i++) {
        int idx = base + i;
        if (idx < N_NODES) {
            int c = cnt[idx];
            rowoff[idx] = running;
            running += c;
            dis[idx] = rsqrtf((float)(c + 1));
        }
    }
    if (t == 1023) rowoff[N_NODES] = part[1023];
}

__global__ void k_fill(const int* __restrict__ ei, const int* __restrict__ rowoff,
                       int* __restrict__ cur, int* __restrict__ csrc)
{
    int e = blockIdx.x * blockDim.x + threadIdx.x;
    if (e < N_EDGES) {
        int s = ei[e];
        int d = ei[N_EDGES + e];
        int pos = rowoff[d] + atomicAdd(&cur[d], 1);
        csrc[pos] = s;
    }
}

// ---------------- TF32 tensor-core GEMM -------------------------------------
// C[M,Ncols] = op(A[M,K]) @ B[K,Ncols] (+bias)(+relu)
// block tile 128x128, BK=32, 8 warps (4 in M x 2 in N), warp tile 32x64
// smem holds tf32 bits (converted once at store); next tile register-prefetched.
__device__ __forceinline__ uint32_t f2tf32(float f) {
    uint32_t r;
    asm("cvt.rna.tf32.f32 %0, %1;" : "=r"(r) : "f"(f));
    return r;
}

template<bool RELU_A, bool BIAS, bool RELU_OUT>
__global__ void __launch_bounds__(256, 2) k_gemm_tc(
    const float* __restrict__ A, const float* __restrict__ B,
    const float* __restrict__ bias, float* __restrict__ C,
    int M, int Ncols, int K)
{
    __shared__ uint32_t As[128][36];   // tf32 bits; bank = 4*row + col (mod 32)
    __shared__ uint32_t Bs[32][132];

    const int tid    = threadIdx.x;
    const int lane   = tid & 31;
    const int wid    = tid >> 5;
    const int warp_m = wid & 3;
    const int warp_n = wid >> 2;
    const int row0   = blockIdx.x * 128;
    const int col0   = blockIdx.y * 128;

    const int g  = lane >> 2;
    const int tg = lane & 3;

    float c[2][8][4];
#pragma unroll
    for (int mf = 0; mf < 2; mf++)
#pragma unroll
        for (int nf = 0; nf < 8; nf++)
#pragma unroll
            for (int i = 0; i < 4; i++) c[mf][nf][i] = 0.0f;

    // global load mapping
    const int a_r  = tid >> 3;          // 0..31 (+32*i)
    const int a_c4 = (tid & 7) * 4;
    const int b_k  = tid >> 5;          // 0..7 (+8*j)
    const int b_c4 = lane * 4;

    float4 pa[4], pb[4];

    // prologue: load tile 0
#pragma unroll
    for (int i = 0; i < 4; i++) {
        int r = a_r + i * 32;
        pa[i] = make_float4(0.f, 0.f, 0.f, 0.f);
        if (row0 + r < M)
            pa[i] = *(const float4*)(A + (size_t)(row0 + r) * K + a_c4);
    }
#pragma unroll
    for (int j = 0; j < 4; j++)
        pb[j] = *(const float4*)(B + (size_t)(b_k + j * 8) * Ncols + col0 + b_c4);

    const int NIT = K / 32;
    for (int it = 0; it < NIT; it++) {
        // store current tile to smem (cvt to tf32, relu on A if requested)
#pragma unroll
        for (int i = 0; i < 4; i++) {
            int r = a_r + i * 32;
            float4 v = pa[i];
            if (RELU_A) {
                v.x = fmaxf(v.x, 0.f); v.y = fmaxf(v.y, 0.f);
                v.z = fmaxf(v.z, 0.f); v.w = fmaxf(v.w, 0.f);
            }
            As[r][a_c4 + 0] = f2tf32(v.x); As[r][a_c4 + 1] = f2tf32(v.y);
            As[r][a_c4 + 2] = f2tf32(v.z); As[r][a_c4 + 3] = f2tf32(v.w);
        }
#pragma unroll
        for (int j = 0; j < 4; j++) {
            int k = b_k + j * 8;
            float4 v = pb[j];
            Bs[k][b_c4 + 0] = f2tf32(v.x); Bs[k][b_c4 + 1] = f2tf32(v.y);
            Bs[k][b_c4 + 2] = f2tf32(v.z); Bs[k][b_c4 + 3] = f2tf32(v.w);
        }
        __syncthreads();

        // prefetch next tile into registers (overlaps with MMA below)
        if (it + 1 < NIT) {
            int k0 = (it + 1) * 32;
#pragma unroll
            for (int i = 0; i < 4; i++) {
                int r = a_r + i * 32;
                pa[i] = make_float4(0.f, 0.f, 0.f, 0.f);
                if (row0 + r < M)
                    pa[i] = *(const float4*)(A + (size_t)(row0 + r) * K + k0 + a_c4);
            }
#pragma unroll
            for (int j = 0; j < 4; j++)
                pb[j] = *(const float4*)(B + (size_t)(k0 + b_k + j * 8) * Ncols + col0 + b_c4);
        }

#pragma unroll
        for (int kk = 0; kk < 4; kk++) {
            const int kb = kk * 8;
            uint32_t af[2][4];
#pragma unroll
            for (int mf = 0; mf < 2; mf++) {
                int rs = warp_m * 32 + mf * 16 + g;
                af[mf][0] = As[rs    ][kb + tg    ];
                af[mf][1] = As[rs + 8][kb + tg    ];
                af[mf][2] = As[rs    ][kb + tg + 4];
                af[mf][3] = As[rs + 8][kb + tg + 4];
            }
            uint32_t bf[8][2];
#pragma unroll
            for (int nf = 0; nf < 8; nf++) {
                int ns = warp_n * 64 + nf * 8 + g;
                bf[nf][0] = Bs[kb + tg    ][ns];
                bf[nf][1] = Bs[kb + tg + 4][ns];
            }
#pragma unroll
            for (int mf = 0; mf < 2; mf++)
#pragma unroll
                for (int nf = 0; nf < 8; nf++) {
                    asm volatile(
                        "mma.sync.aligned.m16n8k8.row.col.f32.tf32.tf32.f32 "
                        "{%0,%1,%2,%3}, {%4,%5,%6,%7}, {%8,%9}, {%0,%1,%2,%3};"
                        : "+f"(c[mf][nf][0]), "+f"(c[mf][nf][1]),
                          "+f"(c[mf][nf][2]), "+f"(c[mf][nf][3])
                        : "r"(af[mf][0]), "r"(af[mf][1]), "r"(af[mf][2]), "r"(af[mf][3]),
                          "r"(bf[nf][0]), "r"(bf[nf][1]));
                }
        }
        __syncthreads();
    }

    // epilogue
#pragma unroll
    for (int mf = 0; mf < 2; mf++) {
        int rbase = row0 + warp_m * 32 + mf * 16 + g;
#pragma unroll
        for (int nf = 0; nf < 8; nf++) {
            int col = col0 + warp_n * 64 + nf * 8 + tg * 2;
            float b0 = 0.f, b1 = 0.f;
            if (BIAS) { b0 = bias[col]; b1 = bias[col + 1]; }
#pragma unroll
            for (int half = 0; half < 2; half++) {
                int r = rbase + half * 8;
                if (r < M) {
                    float v0 = c[mf][nf][half * 2 + 0] + b0;
                    float v1 = c[mf][nf][half * 2 + 1] + b1;
                    if (RELU_OUT) { v0 = fmaxf(v0, 0.f); v1 = fmaxf(v1, 0.f); }
                    float2 o = make_float2(v0, v1);
                    *(float2*)(C + (size_t)r * Ncols + col) = o;
                }
            }
        }
    }
}

// ---------------- CSR gather aggregation (one warp per dst node) ------------
__global__ void __launch_bounds__(256) k_gather(
    const int* __restrict__ csrc, const int* __restrict__ rowoff,
    const float* __restrict__ dis, const float* __restrict__ t,
    const float* __restrict__ bias, float* __restrict__ h)
{
    int w    = (blockIdx.x * 256 + threadIdx.x) >> 5;
    int lane = threadIdx.x & 31;
    if (w >= N_NODES) return;

    int beg = rowoff[w], end = rowoff[w + 1];
    float dd = dis[w];

    float4 acc = make_float4(0.f, 0.f, 0.f, 0.f);
    for (int eb = beg; eb < end; eb += 32) {
        int n = end - eb; if (n > 32) n = 32;
        int   s_l  = (lane < n) ? __ldg(csrc + eb + lane) : 0;
        float ns_l = (lane < n) ? __ldg(dis + s_l) : 0.f;
#pragma unroll 4
        for (int j = 0; j < n; j++) {
            int   s  = __shfl_sync(0xffffffffu, s_l,  j);
            float ns = __shfl_sync(0xffffffffu, ns_l, j);
            float4 v = *(const float4*)(t + (size_t)s * D_HID + lane * 4);
            acc.x = fmaf(ns, v.x, acc.x); acc.y = fmaf(ns, v.y, acc.y);
            acc.z = fmaf(ns, v.z, acc.z); acc.w = fmaf(ns, v.w, acc.w);
        }
    }

    float4 tv = *(const float4*)(t + (size_t)w * D_HID + lane * 4);
    float4 bv = ((const float4*)bias)[lane];
    float dd2 = dd * dd;
    float4 o;
    o.x = fmaf(dd, acc.x, fmaf(dd2, tv.x, bv.x));
    o.y = fmaf(dd, acc.y, fmaf(dd2, tv.y, bv.y));
    o.z = fmaf(dd, acc.z, fmaf(dd2, tv.z, bv.z));
    o.w = fmaf(dd, acc.w, fmaf(dd2, tv.w, bv.w));
    *(float4*)(h + (size_t)w * D_HID + lane * 4) = o;
}

// ---------------- final: out[M,10] = H[M,256] @ W[256,10] + b ---------------
__global__ void __launch_bounds__(256) k_final(
    const float* __restrict__ H, const float* __restrict__ W,
    const float* __restrict__ b, float* __restrict__ out, int M)
{
    __shared__ float sW[D_MLP * D_OUT];
    __shared__ float sb[D_OUT];
    for (int k = threadIdx.x; k < D_MLP * D_OUT; k += 256) sW[k] = W[k];
    if (threadIdx.x < D_OUT) sb[threadIdx.x] = b[threadIdx.x];
    __syncthreads();

    int w    = (blockIdx.x * 256 + threadIdx.x) >> 5;
    int lane = threadIdx.x & 31;
    if (w >= M) return;

    const float* hrow = H + (size_t)w * D_MLP;
    float acc[D_OUT];
#pragma unroll
    for (int j = 0; j < D_OUT; j++) acc[j] = 0.0f;

#pragma unroll
    for (int kk = 0; kk < D_MLP / 32; kk++) {
        int k = kk * 32 + lane;
        float hv = hrow[k];
        const float* wr = &sW[k * D_OUT];
#pragma unroll
        for (int j = 0; j < D_OUT; j++) acc[j] = fmaf(hv, wr[j], acc[j]);
    }
#pragma unroll
    for (int j = 0; j < D_OUT; j++) {
#pragma unroll
        for (int off = 16; off; off >>= 1)
            acc[j] += __shfl_down_sync(0xffffffffu, acc[j], off);
    }
    if (lane == 0) {
#pragma unroll
        for (int j = 0; j < D_OUT; j++)
            out[(size_t)w * D_OUT + j] = acc[j] + sb[j];
    }
}

// ---------------------------------------------------------------------------
extern "C" void kernel_launch(void* const* d_in, const int* in_sizes, int n_in,
                              void* d_out, int out_size)
{
    const float* x   = (const float*)d_in[0];
    const int*   ei  = (const int*)d_in[1];     // int32 (JAX x64 disabled)
    const float* W0  = (const float*)d_in[2];
    const float* b0  = (const float*)d_in[3];
    const float* W1  = (const float*)d_in[4];
    const float* b1  = (const float*)d_in[5];
    const float* Wm1 = (const float*)d_in[6];
    const float* bm1 = (const float*)d_in[7];
    const float* Wm2 = (const float*)d_in[8];
    const float* bm2 = (const float*)d_in[9];
    float* out = (float*)d_out;

    float *dis, *t, *h, *h2;
    int *cnt, *cur, *rowoff, *csrc;
    cudaGetSymbolAddress((void**)&dis, g_dis);
    cudaGetSymbolAddress((void**)&t,   g_t);
    cudaGetSymbolAddress((void**)&h,   g_h);
    cudaGetSymbolAddress((void**)&h2,  g_h2);
    cudaGetSymbolAddress((void**)&cnt, g_cnt);
    cudaGetSymbolAddress((void**)&cur, g_cur);
    cudaGetSymbolAddress((void**)&rowoff, g_rowoff);
    cudaGetSymbolAddress((void**)&csrc, g_csrc);

    // side stream + events for fork/join (created once, on the uncaptured
    // correctness call; host-side objects only, no device allocations)
    static cudaStream_t s_csr = nullptr;
    static cudaEvent_t  ev_fork = nullptr, ev_csr = nullptr;
    if (s_csr == nullptr) {
        cudaStreamCreateWithFlags(&s_csr, cudaStreamNonBlocking);
        cudaEventCreateWithFlags(&ev_fork, cudaEventDisableTiming);
        cudaEventCreateWithFlags(&ev_csr,  cudaEventDisableTiming);
    }

    const int ngrid = (N_NODES + 255) / 256;
    const int egrid = (N_EDGES + 255) / 256;
    const dim3 gemm_grid1((N_NODES + 127) / 128, 1);
    const dim3 gemm_grid2((N_NODES + 127) / 128, 2);
    const int  gather_grid = (N_NODES * 32 + 255) / 256;

    // ---- fork: CSR build on side stream, layer-0 GEMM on main stream ----
    cudaEventRecord(ev_fork, 0);
    cudaStreamWaitEvent(s_csr, ev_fork, 0);

    k_zero <<<ngrid, 256, 0, s_csr>>>(cnt, cur);
    k_count<<<egrid, 256, 0, s_csr>>>(ei, cnt);
    k_scan <<<1, 1024, 0, s_csr>>>(cnt, rowoff, dis);
    k_fill <<<egrid, 256, 0, s_csr>>>(ei, rowoff, cur, csrc);
    cudaEventRecord(ev_csr, s_csr);

    k_gemm_tc<false, false, false><<<gemm_grid1, 256>>>(x, W0, nullptr, t, N_NODES, D_HID, D_IN);

    // ---- join: gather needs both CSR and t ----
    cudaStreamWaitEvent(0, ev_csr, 0);
    k_gather<<<gather_grid, 256>>>(csrc, rowoff, dis, t, b0, h);

    // layer 1 (relu fused into GEMM A-load)
    k_gemm_tc<true, false, false><<<gemm_grid1, 256>>>(h, W1, nullptr, t, N_NODES, D_HID, D_HID);
    k_gather<<<gather_grid, 256>>>(csrc, rowoff, dis, t, b1, h);

    // MLP head
    k_gemm_tc<false, true, true><<<gemm_grid2, 256>>>(h, Wm1, bm1, h2, N_NODES, D_MLP, D_HID);
    k_final<<<(N_NODES * 32 + 255) / 256, 256>>>(h2, Wm2, bm2, out, N_NODES);
}